// round 6
// baseline (speedup 1.0000x reference)
#include <cuda_runtime.h>
#include <math.h>

// SVRaster: 4096 rays vs 16^3 regular voxel grid on [-1,1]^3.
//
// 16 threads per ray. Lane j owns the j-th slab (traversal order) along the
// ray's dominant axis D; since |dU|,|dV| <= |dD| a slab contains <= 5 visited
// cells (<=2 U-crossings + <=2 V-crossings + entry), enumerated by a tiny 2D
// mini-DDA with warp-uniform early exit. Every cell is tested with the EXACT
// reference slab arithmetic (planes i*0.125-1 are exact fp32 == ctr +/- half),
// so extra candidates are harmlessly rejected; hit set == reference exactly.
// Hits are globally tn-ordered by (slab order, walk order). Compositing uses
// linearity in incoming transmittance: local composite with T=1, then a
// width-16 shuffle prefix-product supplies each lane's true T0.

#define GN       16
#define CELL     0.125f
#define BMIN     (-1.0f)
#define MAX_HITS 100
#define GROUP    16
#define BLOCK    128
#define LOC_MAX  6

__device__ __forceinline__ float safe_dir(float d) {
    return (fabsf(d) < 1e-8f) ? ((d >= 0.0f) ? 1e-8f : -1e-8f) : d;
}

__global__ void __launch_bounds__(BLOCK)
svraster_kernel(const float* __restrict__ ro,
                const float* __restrict__ rd,
                const float* __restrict__ vdens,
                const float* __restrict__ vcol,
                float* __restrict__ out,
                int R)
{
    __shared__ int sh_v[LOC_MAX * BLOCK];   // slot-major: conflict-free

    const unsigned FULL = 0xffffffffu;
    const int tid = threadIdx.x;
    const int j   = tid & (GROUP - 1);                     // lane in ray group
    const int r   = (blockIdx.x * BLOCK + tid) >> 4;       // ray id

    const float ox = ro[3 * r + 0], oy = ro[3 * r + 1], oz = ro[3 * r + 2];
    const float dxr = rd[3 * r + 0], dyr = rd[3 * r + 1], dzr = rd[3 * r + 2];

    const float ivx = 1.0f / safe_dir(dxr);
    const float ivy = 1.0f / safe_dir(dyr);
    const float ivz = 1.0f / safe_dir(dzr);

    // Scene-box slab (exact same planes as grid faces).
    float tx0 = (BMIN - ox) * ivx, tx1 = (1.0f - ox) * ivx;
    float ty0 = (BMIN - oy) * ivy, ty1 = (1.0f - oy) * ivy;
    float tz0 = (BMIN - oz) * ivz, tz1 = (1.0f - oz) * ivz;
    float tEnter = fmaxf(fmaxf(fminf(tx0, tx1), fminf(ty0, ty1)), fminf(tz0, tz1));
    float tExit  = fminf(fminf(fmaxf(tx0, tx1), fmaxf(ty0, ty1)), fmaxf(tz0, tz1));
    tEnter = fmaxf(tEnter, 0.0f);

    // Dominant axis D = argmax |d|;  (D,U,V) permutation:
    // axis0: (x,y,z)  axis1: (y,x,z)  axis2: (z,x,y)
    float adx = fabsf(dxr), ady = fabsf(dyr), adz = fabsf(dzr);
    int axis = (adx >= ady && adx >= adz) ? 0 : ((ady >= adz) ? 1 : 2);

    float oD = (axis == 0) ? ox : ((axis == 1) ? oy : oz);
    float oU = (axis == 0) ? oy : ox;
    float oV = (axis == 2) ? oy : oz;
    float iD = (axis == 0) ? ivx : ((axis == 1) ? ivy : ivz);
    float iU = (axis == 0) ? ivy : ivx;
    float iV = (axis == 2) ? ivy : ivz;
    float dUr = (axis == 0) ? dyr : dxr;
    float dVr = (axis == 2) ? dyr : dzr;

    const int sD = (iD >= 0.0f) ? 1 : -1;
    const int sU = (iU >= 0.0f) ? 1 : -1;
    const int sV = (iV >= 0.0f) ? 1 : -1;
    const int exU = (sU > 0) ? 1 : 0;
    const int exV = (sV > 0) ? 1 : 0;

    // Lane j -> slab k in traversal order.
    const int k = (sD > 0) ? j : (GN - 1 - j);

    // Exact D-axis crossings of slab k (== reference per-voxel D slab values).
    float pk0 = fmaf((float)k,       CELL, BMIN);
    float pk1 = fmaf((float)(k + 1), CELL, BMIN);
    float tA = (pk0 - oD) * iD;
    float tB = (pk1 - oD) * iD;
    float lDk = fminf(tA, tB);
    float nDk = fmaxf(tA, tB);

    float w0 = fmaxf(lDk, tEnter);
    float w1 = fminf(nDk, tExit);
    bool alive = (w1 > w0);

    // Starting U/V cells at t = w0 (+ both-direction boundary corrections;
    // extra candidate cells are harmless, missed cells are not).
    float pu = fmaf(dUr, w0, oU);
    float pv = fmaf(dVr, w0, oV);
    int u = (int)floorf((pu - BMIN) * 8.0f);
    int v = (int)floorf((pv - BMIN) * 8.0f);

    float lu = (fmaf((float)(u + 1 - exU), CELL, BMIN) - oU) * iU;
    float nu = (fmaf((float)(u + exU),     CELL, BMIN) - oU) * iU;
    if      (nu < w0) u += sU;       // floor undershot: advance
    else if (lu > w0) u -= sU;       // floor overshot: include predecessor
    lu = (fmaf((float)(u + 1 - exU), CELL, BMIN) - oU) * iU;
    nu = (fmaf((float)(u + exU),     CELL, BMIN) - oU) * iU;

    float lv = (fmaf((float)(v + 1 - exV), CELL, BMIN) - oV) * iV;
    float nv = (fmaf((float)(v + exV),     CELL, BMIN) - oV) * iV;
    if      (nv < w0) v += sV;
    else if (lv > w0) v -= sV;
    lv = (fmaf((float)(v + 1 - exV), CELL, BMIN) - oV) * iV;
    nv = (fmaf((float)(v + exV),     CELL, BMIN) - oV) * iV;

    // Early zero-fill of idx row (stores retire under the DDA's shadow).
    float* out_idx = out + (size_t)5 * R + (size_t)r * MAX_HITS;
    {
        float4 z4 = make_float4(0.0f, 0.0f, 0.0f, 0.0f);
        ((float4*)out_idx)[j] = z4;
        if (j < MAX_HITS / 4 - GROUP) ((float4*)out_idx)[j + GROUP] = z4;
    }

    // ---- per-slab mini-DDA + local composite (T starts at 1) ----
    float Tl = 1.0f, lr = 0.0f, lg = 0.0f, lb = 0.0f, ldep = 0.0f;
    int cnt = 0;

    #pragma unroll 1
    for (int it = 0; it < LOC_MAX; ++it) {
        if (!__ballot_sync(FULL, alive)) break;

        float tn = fmaxf(fmaxf(lu, lv), fmaxf(lDk, 0.0f));
        float tf = fminf(fminf(nu, nv), nDk);
        bool inb = ((unsigned)u < GN) && ((unsigned)v < GN);
        bool hit = alive && inb && (tf > tn);

        if (hit) {
            int ix = (axis == 0) ? k : u;
            int iy = (axis == 0) ? u : ((axis == 1) ? k : v);
            int iz = (axis == 2) ? k : v;
            int vox = (ix * GN + iy) * GN + iz;
            float sg = __expf(__ldg(&vdens[vox]));
            float c0 = __ldg(&vcol[3 * vox + 0]);
            float c1 = __ldg(&vcol[3 * vox + 1]);
            float c2 = __ldg(&vcol[3 * vox + 2]);
            float dt = tf - tn;
            float alpha = 1.0f - __expf(-sg * dt);
            float w = Tl * alpha;
            lr   += w * c0;
            lg   += w * c1;
            lb   += w * c2;
            ldep += w * 0.5f * (tn + tf);
            Tl   *= (1.0f - alpha + 1e-10f);
            sh_v[cnt * BLOCK + tid] = vox;
            cnt++;
        }

        // Step to next cell, or finish when the next crossing leaves window.
        float nmin = fminf(nu, nv);
        if (nmin >= w1) alive = false;
        bool stepU = (nu <= nv);
        if (alive) {
            if (stepU) { u += sU; lu = nu; nu = (fmaf((float)(u + exU), CELL, BMIN) - oU) * iU; }
            else       { v += sV; lv = nv; nv = (fmaf((float)(v + exV), CELL, BMIN) - oV) * iV; }
        }
    }

    // ---- width-16 scans: hit-count prefix sum + transmittance prefix product
    float prod = Tl;
    int   csum = cnt;
    #pragma unroll
    for (int d = 1; d < GROUP; d <<= 1) {
        float p = __shfl_up_sync(FULL, prod, d, GROUP);
        int   c = __shfl_up_sync(FULL, csum, d, GROUP);
        if (j >= d) { prod *= p; csum += c; }
    }
    float T0 = __shfl_up_sync(FULL, prod, 1, GROUP);
    if (j == 0) T0 = 1.0f;
    int base  = csum - cnt;
    int total = __shfl_sync(FULL, csum, GROUP - 1, GROUP);

    // ---- reductions: rgb/depth scale linearly with incoming T0 ----
    float sr = T0 * lr, sg2 = T0 * lg, sb = T0 * lb, sd = T0 * ldep;
    #pragma unroll
    for (int d = GROUP / 2; d > 0; d >>= 1) {
        sr  += __shfl_xor_sync(FULL, sr,  d, GROUP);
        sg2 += __shfl_xor_sync(FULL, sg2, d, GROUP);
        sb  += __shfl_xor_sync(FULL, sb,  d, GROUP);
        sd  += __shfl_xor_sync(FULL, sd,  d, GROUP);
    }

    // ---- outputs ----
    __syncwarp(FULL);   // zero-fill (other lanes) before hit overwrites

    for (int i = 0; i < cnt; ++i)
        out_idx[base + i] = (float)sh_v[i * BLOCK + tid];

    if (j == 0) {
        out[3 * r + 0] = sr;
        out[3 * r + 1] = sg2;
        out[3 * r + 2] = sb;
        out[(size_t)3 * R + r] = sd;
        out[(size_t)4 * R + r] = (float)total;
    }
}

extern "C" void kernel_launch(void* const* d_in, const int* in_sizes, int n_in,
                              void* d_out, int out_size)
{
    const float* ro    = (const float*)d_in[0];
    const float* rd    = (const float*)d_in[1];
    const float* vdens = (const float*)d_in[4];
    const float* vcol  = (const float*)d_in[5];
    float* out = (float*)d_out;

    int R = in_sizes[0] / 3;
    int total_threads = R * GROUP;
    int blocks = (total_threads + BLOCK - 1) / BLOCK;
    svraster_kernel<<<blocks, BLOCK>>>(ro, rd, vdens, vcol, out, R);
}

// round 7
// speedup vs baseline: 1.0258x; 1.0258x over previous
#include <cuda_runtime.h>
#include <math.h>

// SVRaster: 4096 rays vs 16^3 regular voxel grid on [-1,1]^3.
//
// 16 threads per ray. Lane j owns the j-th slab (traversal order) along the
// ray's dominant axis D; since |dU|,|dV| <= |dD| a slab contains <= 5 visited
// cells, enumerated by a tiny 2D mini-DDA, here FULLY UNROLLED (6 iters) and
// BRANCHLESS: loads + exps issue unconditionally (clamped voxel index), the
// hit decision uses the EXACT reference slab arithmetic (planes i*0.125-1
// are exact fp32 == ctr +/- half), and composite updates are selects.
// Hits are globally tn-ordered by (slab order, walk order). Compositing uses
// linearity in incoming transmittance: local composite with T=1, then a
// width-16 shuffle prefix-product supplies each lane's true T0.

#define GN       16
#define CELL     0.125f
#define BMIN     (-1.0f)
#define MAX_HITS 100
#define GROUP    16
#define BLOCK    128
#define LOC_MAX  6

__device__ __forceinline__ float safe_dir(float d) {
    return (fabsf(d) < 1e-8f) ? ((d >= 0.0f) ? 1e-8f : -1e-8f) : d;
}

__global__ void __launch_bounds__(BLOCK)
svraster_kernel(const float* __restrict__ ro,
                const float* __restrict__ rd,
                const float* __restrict__ vdens,
                const float* __restrict__ vcol,
                float* __restrict__ out,
                int R)
{
    __shared__ int sh_v[LOC_MAX * BLOCK];   // slot-major: conflict-free

    const unsigned FULL = 0xffffffffu;
    const int tid = threadIdx.x;
    const int j   = tid & (GROUP - 1);                     // lane in ray group
    const int r   = (blockIdx.x * BLOCK + tid) >> 4;       // ray id

    const float ox = ro[3 * r + 0], oy = ro[3 * r + 1], oz = ro[3 * r + 2];
    const float dxr = rd[3 * r + 0], dyr = rd[3 * r + 1], dzr = rd[3 * r + 2];

    const float ivx = 1.0f / safe_dir(dxr);
    const float ivy = 1.0f / safe_dir(dyr);
    const float ivz = 1.0f / safe_dir(dzr);

    // Scene-box slab (exact same planes as grid faces).
    float tx0 = (BMIN - ox) * ivx, tx1 = (1.0f - ox) * ivx;
    float ty0 = (BMIN - oy) * ivy, ty1 = (1.0f - oy) * ivy;
    float tz0 = (BMIN - oz) * ivz, tz1 = (1.0f - oz) * ivz;
    float tEnter = fmaxf(fmaxf(fminf(tx0, tx1), fminf(ty0, ty1)), fminf(tz0, tz1));
    float tExit  = fminf(fminf(fmaxf(tx0, tx1), fmaxf(ty0, ty1)), fmaxf(tz0, tz1));
    tEnter = fmaxf(tEnter, 0.0f);

    // Dominant axis D = argmax |d|;  (D,U,V) permutation:
    // axis0: (x,y,z)  axis1: (y,x,z)  axis2: (z,x,y)
    float adx = fabsf(dxr), ady = fabsf(dyr), adz = fabsf(dzr);
    int axis = (adx >= ady && adx >= adz) ? 0 : ((ady >= adz) ? 1 : 2);

    float oD = (axis == 0) ? ox : ((axis == 1) ? oy : oz);
    float oU = (axis == 0) ? oy : ox;
    float oV = (axis == 2) ? oy : oz;
    float iD = (axis == 0) ? ivx : ((axis == 1) ? ivy : ivz);
    float iU = (axis == 0) ? ivy : ivx;
    float iV = (axis == 2) ? ivy : ivz;
    float dUr = (axis == 0) ? dyr : dxr;
    float dVr = (axis == 2) ? dyr : dzr;

    const int sD = (iD >= 0.0f) ? 1 : -1;
    const int sU = (iU >= 0.0f) ? 1 : -1;
    const int sV = (iV >= 0.0f) ? 1 : -1;
    const int exU = (sU > 0) ? 1 : 0;
    const int exV = (sV > 0) ? 1 : 0;

    // Lane j -> slab k in traversal order.
    const int k = (sD > 0) ? j : (GN - 1 - j);

    // Exact D-axis crossings of slab k (== reference per-voxel D slab values).
    float pk0 = fmaf((float)k,       CELL, BMIN);
    float pk1 = fmaf((float)(k + 1), CELL, BMIN);
    float tA = (pk0 - oD) * iD;
    float tB = (pk1 - oD) * iD;
    float lDk = fminf(tA, tB);
    float nDk = fmaxf(tA, tB);

    float w0 = fmaxf(lDk, tEnter);
    float w1 = fminf(nDk, tExit);
    bool alive = (w1 > w0);

    // Starting U/V cells at t = w0 (+ both-direction boundary corrections;
    // extra candidate cells are harmless, missed cells are not).
    float pu = fmaf(dUr, w0, oU);
    float pv = fmaf(dVr, w0, oV);
    int u = (int)floorf((pu - BMIN) * 8.0f);
    int v = (int)floorf((pv - BMIN) * 8.0f);

    float lu = (fmaf((float)(u + 1 - exU), CELL, BMIN) - oU) * iU;
    float nu = (fmaf((float)(u + exU),     CELL, BMIN) - oU) * iU;
    if      (nu < w0) u += sU;       // floor undershot: advance
    else if (lu > w0) u -= sU;       // floor overshot: include predecessor
    lu = (fmaf((float)(u + 1 - exU), CELL, BMIN) - oU) * iU;
    nu = (fmaf((float)(u + exU),     CELL, BMIN) - oU) * iU;

    float lv = (fmaf((float)(v + 1 - exV), CELL, BMIN) - oV) * iV;
    float nv = (fmaf((float)(v + exV),     CELL, BMIN) - oV) * iV;
    if      (nv < w0) v += sV;
    else if (lv > w0) v -= sV;
    lv = (fmaf((float)(v + 1 - exV), CELL, BMIN) - oV) * iV;
    nv = (fmaf((float)(v + exV),     CELL, BMIN) - oV) * iV;

    // Early zero-fill of idx row (stores retire under the DDA's shadow).
    float* out_idx = out + (size_t)5 * R + (size_t)r * MAX_HITS;
    {
        float4 z4 = make_float4(0.0f, 0.0f, 0.0f, 0.0f);
        ((float4*)out_idx)[j] = z4;
        if (j < MAX_HITS / 4 - GROUP) ((float4*)out_idx)[j + GROUP] = z4;
    }

    // ---- per-slab mini-DDA + local composite: fully unrolled, branchless ----
    float Tl = 1.0f, lr = 0.0f, lg = 0.0f, lb = 0.0f, ldep = 0.0f;
    int cnt = 0;

    #pragma unroll
    for (int it = 0; it < LOC_MAX; ++it) {
        float tn = fmaxf(fmaxf(lu, lv), fmaxf(lDk, 0.0f));
        float tf = fminf(fminf(nu, nv), nDk);
        bool inb = ((unsigned)u < GN) && ((unsigned)v < GN);
        bool hit = alive && inb && (tf > tn);

        // Clamped voxel index: loads are always valid; hit gate is exact.
        int uc = min(GN - 1, max(0, u));
        int vc = min(GN - 1, max(0, v));
        int ix = (axis == 0) ? k : uc;
        int iy = (axis == 0) ? uc : ((axis == 1) ? k : vc);
        int iz = (axis == 2) ? k : vc;
        int vox = (ix * GN + iy) * GN + iz;

        // Unconditional loads + exps: schedulable early, no divergence.
        float sg = __expf(__ldg(&vdens[vox]));
        float c0 = __ldg(&vcol[3 * vox + 0]);
        float c1 = __ldg(&vcol[3 * vox + 1]);
        float c2 = __ldg(&vcol[3 * vox + 2]);
        float dt = tf - tn;
        float alpha = 1.0f - __expf(-sg * dt);

        float w = hit ? (Tl * alpha) : 0.0f;
        lr   = fmaf(w, c0, lr);
        lg   = fmaf(w, c1, lg);
        lb   = fmaf(w, c2, lb);
        ldep = fmaf(w, 0.5f * (tn + tf), ldep);
        Tl  *= hit ? (1.0f - alpha + 1e-10f) : 1.0f;

        // Unconditional record into slot `cnt` (max slot 5); advance on hit.
        sh_v[cnt * BLOCK + tid] = vox;
        cnt += hit ? 1 : 0;

        // Branchless step; freeze state once the next crossing leaves window.
        float nmin = fminf(nu, nv);
        bool cont  = alive && (nmin < w1);
        bool stepU = cont && (nu <= nv);
        bool stepV = cont && !(nu <= nv);
        alive = cont;

        u += stepU ? sU : 0;
        v += stepV ? sV : 0;
        lu = stepU ? nu : lu;
        lv = stepV ? nv : lv;
        float nuN = (fmaf((float)(u + exU), CELL, BMIN) - oU) * iU;
        float nvN = (fmaf((float)(v + exV), CELL, BMIN) - oV) * iV;
        nu = stepU ? nuN : nu;
        nv = stepV ? nvN : nv;
    }

    // ---- width-16 scans: hit-count prefix sum + transmittance prefix product
    float prod = Tl;
    int   csum = cnt;
    #pragma unroll
    for (int d = 1; d < GROUP; d <<= 1) {
        float p = __shfl_up_sync(FULL, prod, d, GROUP);
        int   c = __shfl_up_sync(FULL, csum, d, GROUP);
        if (j >= d) { prod *= p; csum += c; }
    }
    float T0 = __shfl_up_sync(FULL, prod, 1, GROUP);
    if (j == 0) T0 = 1.0f;
    int base  = csum - cnt;
    int total = __shfl_sync(FULL, csum, GROUP - 1, GROUP);

    // ---- reductions: rgb/depth scale linearly with incoming T0 ----
    float sr = T0 * lr, sg2 = T0 * lg, sb = T0 * lb, sd = T0 * ldep;
    #pragma unroll
    for (int d = GROUP / 2; d > 0; d >>= 1) {
        sr  += __shfl_xor_sync(FULL, sr,  d, GROUP);
        sg2 += __shfl_xor_sync(FULL, sg2, d, GROUP);
        sb  += __shfl_xor_sync(FULL, sb,  d, GROUP);
        sd  += __shfl_xor_sync(FULL, sd,  d, GROUP);
    }

    // ---- outputs ----
    __syncwarp(FULL);   // zero-fill (other lanes) before hit overwrites

    for (int i = 0; i < cnt; ++i)
        out_idx[base + i] = (float)sh_v[i * BLOCK + tid];

    if (j == 0) {
        out[3 * r + 0] = sr;
        out[3 * r + 1] = sg2;
        out[3 * r + 2] = sb;
        out[(size_t)3 * R + r] = sd;
        out[(size_t)4 * R + r] = (float)total;
    }
}

extern "C" void kernel_launch(void* const* d_in, const int* in_sizes, int n_in,
                              void* d_out, int out_size)
{
    const float* ro    = (const float*)d_in[0];
    const float* rd    = (const float*)d_in[1];
    const float* vdens = (const float*)d_in[4];
    const float* vcol  = (const float*)d_in[5];
    float* out = (float*)d_out;

    int R = in_sizes[0] / 3;
    int total_threads = R * GROUP;
    int blocks = (total_threads + BLOCK - 1) / BLOCK;
    svraster_kernel<<<blocks, BLOCK>>>(ro, rd, vdens, vcol, out, R);
}